// round 1
// baseline (speedup 1.0000x reference)
#include <cuda_runtime.h>
#include <cuda_bf16.h>

#define BS   128
#define OBJ  512
#define RNN  1024
#define HID  512
#define KCHUNKS 8

// Partial GEMM results: [kchunk][b][hid]. Summed (with bias) in attn kernel
// so we avoid float atomics (deterministic) and any init kernel.
__device__ float g_part[KCHUNKS * BS * HID];

__device__ __forceinline__ float tanh_fast(float x) {
    float y;
    asm("tanh.approx.f32 %0, %1;" : "=f"(y) : "f"(x));
    return y;
}

// att_h partials: grid (16 n-tiles of 32, 8 k-chunks of 128), 256 threads.
// out_part[b][n] = sum_{k in chunk} h[b][k] * W[n][k]
__global__ __launch_bounds__(256) void gemm_kernel(
    const float* __restrict__ h, const float* __restrict__ W)
{
    __shared__ float h_s[64][129];   // [k][b], padded
    __shared__ float w_s[64][33];    // [k][j], padded
    const int n0 = blockIdx.x * 32;
    const int k0 = blockIdx.y * 128;
    const int t  = threadIdx.x;
    const int tm = t & 31;    // m-lane: rows tm, tm+32, tm+64, tm+96
    const int tn = t >> 5;    // n-lane: cols tn, tn+8, tn+16, tn+24

    float acc[4][4] = {};

    for (int kk = 0; kk < 128; kk += 64) {
        // stage h chunk: 128 b x 64 k, stored k-major (transposed)
        #pragma unroll
        for (int r = 0; r < 8; ++r) {
            int f  = t + 256 * r;       // 2048 float4 total
            int b  = f >> 4;            // 16 float4 per b-row
            int kg = f & 15;
            float4 v = *(const float4*)(h + b * RNN + k0 + kk + kg * 4);
            h_s[kg*4+0][b] = v.x; h_s[kg*4+1][b] = v.y;
            h_s[kg*4+2][b] = v.z; h_s[kg*4+3][b] = v.w;
        }
        // stage W chunk: 32 j x 64 k, k-major
        #pragma unroll
        for (int r = 0; r < 2; ++r) {
            int f  = t + 256 * r;       // 512 float4 total
            int j  = f >> 4;
            int kg = f & 15;
            float4 v = *(const float4*)(W + (n0 + j) * RNN + k0 + kk + kg * 4);
            w_s[kg*4+0][j] = v.x; w_s[kg*4+1][j] = v.y;
            w_s[kg*4+2][j] = v.z; w_s[kg*4+3][j] = v.w;
        }
        __syncthreads();
        #pragma unroll 8
        for (int k = 0; k < 64; ++k) {
            float a0 = h_s[k][tm],      a1 = h_s[k][tm + 32],
                  a2 = h_s[k][tm + 64], a3 = h_s[k][tm + 96];
            float b0 = w_s[k][tn],      b1 = w_s[k][tn + 8],
                  b2 = w_s[k][tn + 16], b3 = w_s[k][tn + 24];
            acc[0][0] += a0*b0; acc[0][1] += a0*b1; acc[0][2] += a0*b2; acc[0][3] += a0*b3;
            acc[1][0] += a1*b0; acc[1][1] += a1*b1; acc[1][2] += a1*b2; acc[1][3] += a1*b3;
            acc[2][0] += a2*b0; acc[2][1] += a2*b1; acc[2][2] += a2*b2; acc[2][3] += a2*b3;
            acc[3][0] += a3*b0; acc[3][1] += a3*b1; acc[3][2] += a3*b2; acc[3][3] += a3*b3;
        }
        __syncthreads();
    }

    float* outp = g_part + blockIdx.y * (BS * HID);
    #pragma unroll
    for (int i = 0; i < 4; ++i)
        #pragma unroll
        for (int j = 0; j < 4; ++j)
            outp[(tm + 32*i) * HID + n0 + tn + 8*j] = acc[i][j];
}

// One block per batch row. Streams att_feats (1MB/block), tanh+dot into
// scores, masked softmax. b_alpha cancels in softmax and is dropped; the
// softmax->mask->renorm chain collapses to a masked softmax.
__global__ __launch_bounds__(1024) void attn_kernel(
    const float* __restrict__ att_feats,
    const int*   __restrict__ att_masks,
    const float* __restrict__ b_h2att,
    const float* __restrict__ w_alpha,
    float*       __restrict__ out)
{
    const int b = blockIdx.x;
    __shared__ float ah[HID];
    __shared__ float wa[HID];
    __shared__ float sc[OBJ];
    __shared__ float red[32];
    const int t = threadIdx.x;

    if (t < HID) {
        float s = b_h2att[t];
        #pragma unroll
        for (int c = 0; c < KCHUNKS; ++c)
            s += g_part[c * (BS * HID) + b * HID + t];
        ah[t] = s;
        wa[t] = w_alpha[t];
    }
    __syncthreads();

    const int w = t >> 5, lane = t & 31;
    const float4* base = (const float4*)(att_feats + (size_t)b * OBJ * HID);
    const float4* ah4  = (const float4*)ah;
    const float4* wa4  = (const float4*)wa;

    for (int o = w; o < OBJ; o += 32) {
        const float4* row = base + o * (HID / 4);
        float s = 0.f;
        #pragma unroll
        for (int i = 0; i < 4; ++i) {
            int idx = lane + 32 * i;
            float4 f  = row[idx];
            float4 a  = ah4[idx];
            float4 wv = wa4[idx];
            s += tanh_fast(f.x + a.x) * wv.x;
            s += tanh_fast(f.y + a.y) * wv.y;
            s += tanh_fast(f.z + a.z) * wv.z;
            s += tanh_fast(f.w + a.w) * wv.w;
        }
        #pragma unroll
        for (int d = 16; d; d >>= 1) s += __shfl_xor_sync(0xffffffffu, s, d);
        if (lane == 0) sc[o] = s;
    }
    __syncthreads();

    // ---- block max over 512 scores ----
    float v = -3.402823466e38f;
    if (t < OBJ) v = sc[t];
    #pragma unroll
    for (int d = 16; d; d >>= 1) v = fmaxf(v, __shfl_xor_sync(0xffffffffu, v, d));
    if (lane == 0) red[w] = v;
    __syncthreads();
    if (w == 0) {
        float m = red[lane];
        #pragma unroll
        for (int d = 16; d; d >>= 1) m = fmaxf(m, __shfl_xor_sync(0xffffffffu, m, d));
        if (lane == 0) red[0] = m;
    }
    __syncthreads();
    const float mx = red[0];

    // ---- masked exp + block sum ----
    float e = 0.f;
    if (t < OBJ) {
        float m = (float)att_masks[b * OBJ + t];
        e = m * __expf(sc[t] - mx);
    }
    float s = e;
    #pragma unroll
    for (int d = 16; d; d >>= 1) s += __shfl_xor_sync(0xffffffffu, s, d);
    __syncthreads();               // mx consumed before red is reused
    if (lane == 0) red[w] = s;
    __syncthreads();
    if (w == 0) {
        float z = red[lane];
        #pragma unroll
        for (int d = 16; d; d >>= 1) z += __shfl_xor_sync(0xffffffffu, z, d);
        if (lane == 0) red[0] = z;
    }
    __syncthreads();
    const float inv = 1.f / red[0];
    if (t < OBJ) out[b * OBJ + t] = e * inv;
}

extern "C" void kernel_launch(void* const* d_in, const int* in_sizes, int n_in,
                              void* d_out, int out_size) {
    const float* h         = (const float*)d_in[0];
    const float* att_feats = (const float*)d_in[1];
    const int*   att_masks = (const int*)  d_in[2];
    const float* W_h2att   = (const float*)d_in[3];
    const float* b_h2att   = (const float*)d_in[4];
    const float* w_alpha   = (const float*)d_in[5];
    // d_in[6] = b_alpha: cancels in softmax, unused.
    float* out = (float*)d_out;

    gemm_kernel<<<dim3(16, 8), 256>>>(h, W_h2att);
    attn_kernel<<<BS, 1024>>>(att_feats, att_masks, b_h2att, w_alpha, out);
}

// round 2
// speedup vs baseline: 1.0037x; 1.0037x over previous
#include <cuda_runtime.h>
#include <cuda_bf16.h>

#define BS   128
#define OBJ  512
#define RNN  1024
#define HID  512
#define KCHUNKS 16   // k-chunks of 64

// GEMM partials: [kchunk][b][hid] (4MB). Summed with bias in scores kernel
// -> deterministic, no atomics, no init kernel.
__device__ float g_part[KCHUNKS * BS * HID];
// Score scratch: [b][obj]
__device__ float g_scores[BS * OBJ];

__device__ __forceinline__ float tanh_fast(float x) {
    float y;
    asm("tanh.approx.f32 %0, %1;" : "=f"(y) : "f"(x));
    return y;
}

// ---------------- GEMM: att_h partials ----------------
// grid (16 n-tiles of 32, 16 k-chunks of 64), 256 threads, ~21KB smem
// -> 2 blocks/SM, 16 warps. out_part[b][n] = sum_{k in chunk} h[b][k]*W[n][k]
__global__ __launch_bounds__(256) void gemm_kernel(
    const float* __restrict__ h, const float* __restrict__ W)
{
    __shared__ float h_s[32][129];   // [k][b], padded
    __shared__ float w_s[32][33];    // [k][j], padded
    const int n0 = blockIdx.x * 32;
    const int k0 = blockIdx.y * 64;
    const int t  = threadIdx.x;
    const int tm = t & 31;    // rows tm, +32, +64, +96
    const int tn = t >> 5;    // cols tn, +8, +16, +24

    float acc[4][4] = {};

    #pragma unroll
    for (int kk = 0; kk < 64; kk += 32) {
        // stage h chunk: 128 b x 32 k, k-major. 1024 float4 / 256 thr
        #pragma unroll
        for (int r = 0; r < 4; ++r) {
            int f  = t + 256 * r;
            int b  = f >> 3;            // 8 float4 per b-row
            int kg = f & 7;
            float4 v = *(const float4*)(h + b * RNN + k0 + kk + kg * 4);
            h_s[kg*4+0][b] = v.x; h_s[kg*4+1][b] = v.y;
            h_s[kg*4+2][b] = v.z; h_s[kg*4+3][b] = v.w;
        }
        // stage W chunk: 32 j x 32 k. 256 float4
        {
            int j  = t >> 3;
            int kg = t & 7;
            float4 v = *(const float4*)(W + (n0 + j) * RNN + k0 + kk + kg * 4);
            w_s[kg*4+0][j] = v.x; w_s[kg*4+1][j] = v.y;
            w_s[kg*4+2][j] = v.z; w_s[kg*4+3][j] = v.w;
        }
        __syncthreads();
        #pragma unroll 8
        for (int k = 0; k < 32; ++k) {
            float a0 = h_s[k][tm],      a1 = h_s[k][tm + 32],
                  a2 = h_s[k][tm + 64], a3 = h_s[k][tm + 96];
            float b0 = w_s[k][tn],      b1 = w_s[k][tn + 8],
                  b2 = w_s[k][tn + 16], b3 = w_s[k][tn + 24];
            acc[0][0] += a0*b0; acc[0][1] += a0*b1; acc[0][2] += a0*b2; acc[0][3] += a0*b3;
            acc[1][0] += a1*b0; acc[1][1] += a1*b1; acc[1][2] += a1*b2; acc[1][3] += a1*b3;
            acc[2][0] += a2*b0; acc[2][1] += a2*b1; acc[2][2] += a2*b2; acc[2][3] += a2*b3;
            acc[3][0] += a3*b0; acc[3][1] += a3*b1; acc[3][2] += a3*b2; acc[3][3] += a3*b3;
        }
        __syncthreads();
    }

    float* outp = g_part + blockIdx.y * (BS * HID);
    #pragma unroll
    for (int i = 0; i < 4; ++i)
        #pragma unroll
        for (int j = 0; j < 4; ++j)
            outp[(tm + 32*i) * HID + n0 + tn + 8*j] = acc[i][j];
}

// ---------------- Scores: tanh + rank-1 dot ----------------
// grid 512 (= 128 b x 4 obj-chunks of 128), 256 threads. Streams att_feats
// (256KB/block); b_alpha dropped (cancels in softmax).
__global__ __launch_bounds__(256) void scores_kernel(
    const float* __restrict__ att_feats,
    const float* __restrict__ b_h2att,
    const float* __restrict__ w_alpha)
{
    const int b     = blockIdx.x >> 2;
    const int chunk = blockIdx.x & 3;
    __shared__ float ah[HID];
    __shared__ float wa[HID];
    const int t = threadIdx.x;

    #pragma unroll
    for (int e = 0; e < 2; ++e) {
        int idx = t + 256 * e;
        float s = b_h2att[idx];
        #pragma unroll
        for (int c = 0; c < KCHUNKS; ++c)
            s += g_part[c * (BS * HID) + b * HID + idx];
        ah[idx] = s;
        wa[idx] = w_alpha[idx];
    }
    __syncthreads();

    const int w = t >> 5, lane = t & 31;
    const float4* base = (const float4*)(att_feats
                         + (size_t)b * OBJ * HID + (size_t)chunk * 128 * HID);
    const float4* ah4  = (const float4*)ah;
    const float4* wa4  = (const float4*)wa;

    for (int o = w; o < 128; o += 8) {
        const float4* row = base + o * (HID / 4);
        float s = 0.f;
        #pragma unroll
        for (int i = 0; i < 4; ++i) {
            int idx = lane + 32 * i;
            float4 f  = row[idx];
            float4 a  = ah4[idx];
            float4 wv = wa4[idx];
            s += tanh_fast(f.x + a.x) * wv.x;
            s += tanh_fast(f.y + a.y) * wv.y;
            s += tanh_fast(f.z + a.z) * wv.z;
            s += tanh_fast(f.w + a.w) * wv.w;
        }
        #pragma unroll
        for (int d = 16; d; d >>= 1) s += __shfl_xor_sync(0xffffffffu, s, d);
        if (lane == 0) g_scores[b * OBJ + chunk * 128 + o] = s;
    }
}

// ---------------- Masked softmax ----------------
// grid 128, 512 threads. softmax->mask->renorm collapses to masked softmax.
__global__ __launch_bounds__(512) void softmax_kernel(
    const int* __restrict__ att_masks, float* __restrict__ out)
{
    const int b = blockIdx.x;
    const int t = threadIdx.x;
    const int w = t >> 5, lane = t & 31;
    __shared__ float red[16];

    float sc = g_scores[b * OBJ + t];

    float v = sc;
    #pragma unroll
    for (int d = 16; d; d >>= 1) v = fmaxf(v, __shfl_xor_sync(0xffffffffu, v, d));
    if (lane == 0) red[w] = v;
    __syncthreads();
    if (w == 0) {
        float m = red[lane & 15];
        #pragma unroll
        for (int d = 8; d; d >>= 1) m = fmaxf(m, __shfl_xor_sync(0xffffffffu, m, d));
        if (lane == 0) red[0] = m;
    }
    __syncthreads();
    const float mx = red[0];

    float m = (float)att_masks[b * OBJ + t];
    float e = m * __expf(sc - mx);
    float s = e;
    #pragma unroll
    for (int d = 16; d; d >>= 1) s += __shfl_xor_sync(0xffffffffu, s, d);
    __syncthreads();
    if (lane == 0) red[w] = s;
    __syncthreads();
    if (w == 0) {
        float z = red[lane & 15];
        #pragma unroll
        for (int d = 8; d; d >>= 1) z += __shfl_xor_sync(0xffffffffu, z, d);
        if (lane == 0) red[0] = z;
    }
    __syncthreads();
    out[b * OBJ + t] = e * (1.f / red[0]);
}

extern "C" void kernel_launch(void* const* d_in, const int* in_sizes, int n_in,
                              void* d_out, int out_size) {
    const float* h         = (const float*)d_in[0];
    const float* att_feats = (const float*)d_in[1];
    const int*   att_masks = (const int*)  d_in[2];
    const float* W_h2att   = (const float*)d_in[3];
    const float* b_h2att   = (const float*)d_in[4];
    const float* w_alpha   = (const float*)d_in[5];
    // d_in[6] = b_alpha: cancels in softmax, unused.
    float* out = (float*)d_out;

    gemm_kernel<<<dim3(16, 16), 256>>>(h, W_h2att);
    scores_kernel<<<512, 256>>>(att_feats, b_h2att, w_alpha);
    softmax_kernel<<<BS, 512>>>(att_masks, out);
}